// round 1
// baseline (speedup 1.0000x reference)
#include <cuda_runtime.h>
#include <math.h>

// Problem dims (fixed)
#define BN 8
#define SN 128
#define TN 512
#define DT 256
#define DF 80

#define NEGV (-1e9f)

// Scratch (static __device__ — no allocation allowed)
__device__ float g_ht[BN * SN * DT];   // text features after conv stack  (B,S,256)
__device__ float g_mt[BN * TN * DT];   // feat features after conv stack  (B,T,256)
__device__ float W1t[DT * 3 * DT];     // [(ci*3+k)][c]
__device__ float W2t[DT * DT];         // [ci][c]
__device__ float F1t[DF * 3 * DT];     // [(ci*3+k)][c]
__device__ float F2t[DT * 3 * DT];
__device__ float F3t[DT * DT];

// ---------------------------------------------------------------------------
// Weight transposition: make inner-loop weight reads coalesced over channel c.
// ---------------------------------------------------------------------------
__global__ void prep_weights_kernel(const float* __restrict__ W1, const float* __restrict__ W2,
                                    const float* __restrict__ F1, const float* __restrict__ F2,
                                    const float* __restrict__ F3) {
    int i = blockIdx.x * blockDim.x + threadIdx.x;
    const int n1 = DT * DT * 3;   // 196608
    const int n2 = DT * DT;       // 65536
    const int n3 = DF * 3 * DT;   // 61440
    const int n4 = DT * DT * 3;
    const int n5 = DT * DT;
    if (i < n1) { W1t[i] = W1[(i & 255) * (DT * 3) + (i >> 8)]; return; }
    i -= n1;
    if (i < n2) { W2t[i] = W2[(i & 255) * DT + (i >> 8)]; return; }
    i -= n2;
    if (i < n3) { F1t[i] = F1[(i & 255) * (DF * 3) + (i >> 8)]; return; }
    i -= n3;
    if (i < n4) { F2t[i] = F2[(i & 255) * (DT * 3) + (i >> 8)]; return; }
    i -= n4;
    if (i < n5) { F3t[i] = F3[(i & 255) * DT + (i >> 8)]; }
}

// ---------------------------------------------------------------------------
// Text path: conv3(W1)+b1 -> relu -> conv1(W2)+b2.  Tile: 16 positions/block.
// grid (B, S/16), 256 threads (one output channel each).
// ---------------------------------------------------------------------------
__global__ __launch_bounds__(256) void text_conv_kernel(const float* __restrict__ h,
                                                        const float* __restrict__ b1,
                                                        const float* __restrict__ b2) {
    const int TS = 16;
    __shared__ float sh_h[TS + 2][DT];     // input rows s0-1 .. s0+TS
    __shared__ float sh_y[DT][17];         // relu(conv1) transposed for stage 2
    int b = blockIdx.x, s0 = blockIdx.y * TS;
    int tid = threadIdx.x;   // = channel c
    // load input window (row s0-1+p), coalesced over channels
    for (int p = 0; p < TS + 2; ++p) {
        int s = s0 - 1 + p;
        float v = 0.f;
        if (s >= 0 && s < SN) v = h[((size_t)(b * SN + s)) * DT + tid];
        sh_h[p][tid] = v;
    }
    __syncthreads();
    int c = tid;
    float acc[TS];
    float bb = b1[c];
#pragma unroll
    for (int p = 0; p < TS; ++p) acc[p] = bb;
    for (int ci = 0; ci < DT; ++ci) {
#pragma unroll
        for (int k = 0; k < 3; ++k) {
            float w = W1t[(ci * 3 + k) * DT + c];
#pragma unroll
            for (int p = 0; p < TS; ++p) acc[p] = fmaf(w, sh_h[p + k][ci], acc[p]);
        }
    }
#pragma unroll
    for (int p = 0; p < TS; ++p) sh_y[c][p] = fmaxf(acc[p], 0.f);
    __syncthreads();
    float a2[TS];
    float bb2 = b2[c];
#pragma unroll
    for (int p = 0; p < TS; ++p) a2[p] = bb2;
    for (int ci = 0; ci < DT; ++ci) {
        float w = W2t[ci * DT + c];
#pragma unroll
        for (int p = 0; p < TS; ++p) a2[p] = fmaf(w, sh_y[ci][p], a2[p]);
    }
#pragma unroll
    for (int p = 0; p < TS; ++p)
        g_ht[((size_t)(b * SN + s0 + p)) * DT + c] = a2[p];
}

// ---------------------------------------------------------------------------
// Feat path: conv3(F1)+g1 -> relu -> conv3(F2)+g2 -> relu -> conv1(F3)+g3.
// Tile: 16 positions/block with halo.  grid (B, T/16), 256 threads.
// ---------------------------------------------------------------------------
__global__ __launch_bounds__(256) void feat_conv_kernel(const float* __restrict__ m,
                                                        const float* __restrict__ g1v,
                                                        const float* __restrict__ g2v,
                                                        const float* __restrict__ g3v) {
    const int TT = 16;
    __shared__ float sh_m[TT + 4][DF];   // m rows t0-2 .. t0+TT+1
    __shared__ float sh_a[DT][19];       // relu(y1), 18 positions (t0-1 .. t0+TT)
    __shared__ float sh_b[DT][17];       // relu(y2), 16 positions
    int b = blockIdx.x, t0 = blockIdx.y * TT;
    int tid = threadIdx.x;
    for (int idx = tid; idx < (TT + 4) * DF; idx += 256) {
        int p = idx / DF, ci = idx % DF;
        int t = t0 - 2 + p;
        sh_m[p][ci] = (t >= 0 && t < TN) ? m[((size_t)(b * TN + t)) * DF + ci] : 0.f;
    }
    __syncthreads();
    int c = tid;
    // stage 1: y1 over 18 positions (global t = t0-1+p)
    {
        float a1[TT + 2];
        float bb = g1v[c];
#pragma unroll
        for (int p = 0; p < TT + 2; ++p) a1[p] = bb;
        for (int ci = 0; ci < DF; ++ci) {
#pragma unroll
            for (int k = 0; k < 3; ++k) {
                float w = F1t[(ci * 3 + k) * DT + c];
#pragma unroll
                for (int p = 0; p < TT + 2; ++p) a1[p] = fmaf(w, sh_m[p + k][ci], a1[p]);
            }
        }
#pragma unroll
        for (int p = 0; p < TT + 2; ++p) sh_a[c][p] = fmaxf(a1[p], 0.f);
    }
    __syncthreads();
    // stage 2: y2 over 16 positions (global t = t0+p)
    {
        float a2[TT];
        float bb = g2v[c];
#pragma unroll
        for (int p = 0; p < TT; ++p) a2[p] = bb;
        for (int ci = 0; ci < DT; ++ci) {
#pragma unroll
            for (int k = 0; k < 3; ++k) {
                float w = F2t[(ci * 3 + k) * DT + c];
#pragma unroll
                for (int p = 0; p < TT; ++p) a2[p] = fmaf(w, sh_a[ci][p + k], a2[p]);
            }
        }
#pragma unroll
        for (int p = 0; p < TT; ++p) sh_b[c][p] = fmaxf(a2[p], 0.f);
    }
    __syncthreads();
    // stage 3: y3 = conv1
    {
        float a3[TT];
        float bb = g3v[c];
#pragma unroll
        for (int p = 0; p < TT; ++p) a3[p] = bb;
        for (int ci = 0; ci < DT; ++ci) {
            float w = F3t[ci * DT + c];
#pragma unroll
            for (int p = 0; p < TT; ++p) a3[p] = fmaf(w, sh_b[ci][p], a3[p]);
        }
#pragma unroll
        for (int p = 0; p < TT; ++p)
            g_mt[((size_t)(b * TN + t0 + p)) * DT + c] = a3[p];
    }
}

// ---------------------------------------------------------------------------
// Pairwise L2 distance + mask + log_softmax over S.  Tile: all 128 s x 32 t
// per block.  grid (B, T/32), 256 threads.  Also zeroes the a_hard region.
// ---------------------------------------------------------------------------
__global__ __launch_bounds__(256) void dist_softmax_kernel(const int* __restrict__ tokl,
                                                           float* __restrict__ out) {
    __shared__ float A[SN][33];
    __shared__ float Bm[32][33];
    __shared__ float Z[SN][33];
    __shared__ float mls[32];
    int b = blockIdx.x, t0 = blockIdx.y * 32;
    int tid = threadIdx.x;
    int ts = tid >> 3, tt = tid & 7;   // thread computes 4x4 microtile: s=4*ts+r, t=4*tt+j
    float acc[4][4];
#pragma unroll
    for (int r = 0; r < 4; ++r)
#pragma unroll
        for (int j = 0; j < 4; ++j) acc[r][j] = 0.f;

    for (int kc = 0; kc < DT / 32; ++kc) {
        int k0 = kc * 32;
        for (int idx = tid; idx < SN * 32; idx += 256) {
            int s = idx >> 5, kk = idx & 31;
            A[s][kk] = g_ht[((size_t)(b * SN + s)) * DT + k0 + kk];
        }
        for (int idx = tid; idx < 32 * 32; idx += 256) {
            int tl = idx >> 5, kk = idx & 31;
            Bm[tl][kk] = g_mt[((size_t)(b * TN + t0 + tl)) * DT + k0 + kk];
        }
        __syncthreads();
#pragma unroll 4
        for (int kk = 0; kk < 32; ++kk) {
            float av[4], bv[4];
#pragma unroll
            for (int r = 0; r < 4; ++r) av[r] = A[ts * 4 + r][kk];
#pragma unroll
            for (int j = 0; j < 4; ++j) bv[j] = Bm[tt * 4 + j][kk];
#pragma unroll
            for (int r = 0; r < 4; ++r)
#pragma unroll
                for (int j = 0; j < 4; ++j) {
                    float d = av[r] - bv[j];
                    acc[r][j] = fmaf(d, d, acc[r][j]);
                }
        }
        __syncthreads();
    }
    int tok = tokl[b];
#pragma unroll
    for (int r = 0; r < 4; ++r) {
        int s = ts * 4 + r;
        float dist;
#pragma unroll
        for (int j = 0; j < 4; ++j) {
            dist = (s < tok) ? sqrtf(fmaxf(acc[r][j], 0.f)) : 0.f;
            Z[s][tt * 4 + j] = -dist;
        }
    }
    __syncthreads();
    // column log-softmax over s: 8 threads per t-column (consecutive lanes)
    int tcol = tid >> 3, l = tid & 7;
    float mx = -3.4e38f;
#pragma unroll
    for (int i2 = 0; i2 < 16; ++i2) mx = fmaxf(mx, Z[l * 16 + i2][tcol]);
    mx = fmaxf(mx, __shfl_xor_sync(0xffffffffu, mx, 4));
    mx = fmaxf(mx, __shfl_xor_sync(0xffffffffu, mx, 2));
    mx = fmaxf(mx, __shfl_xor_sync(0xffffffffu, mx, 1));
    float sm = 0.f;
#pragma unroll
    for (int i2 = 0; i2 < 16; ++i2) sm += expf(Z[l * 16 + i2][tcol] - mx);
    sm += __shfl_xor_sync(0xffffffffu, sm, 4);
    sm += __shfl_xor_sync(0xffffffffu, sm, 2);
    sm += __shfl_xor_sync(0xffffffffu, sm, 1);
    if (l == 0) mls[tcol] = mx + logf(sm);
    __syncthreads();
    float* out_log = out + BN * SN;
    float* out_hard = out + BN * SN + (size_t)BN * SN * TN;
    for (int idx = tid; idx < SN * 32; idx += 256) {
        int s = idx >> 5, tl = idx & 31;
        size_t o = ((size_t)(b * SN + s)) * TN + t0 + tl;
        out_log[o] = Z[s][tl] - mls[tl];
        out_hard[o] = 0.f;   // zero-init a_hard (MAS writes the ones afterwards)
    }
}

// ---------------------------------------------------------------------------
// MAS: forward DP entirely inside warp 0 (4 rows/lane, shfl for s-1 neighbor);
// warps 0-3 cooperatively double-buffer log_a_soft columns into shared.
// Backtrack by thread 0.  grid (B), 128 threads.
// ---------------------------------------------------------------------------
__global__ __launch_bounds__(128) void mas_kernel(const int* __restrict__ tokl,
                                                  const int* __restrict__ featl,
                                                  float* __restrict__ out) {
    const int CH = 16;                       // j-columns per chunk
    __shared__ float4 lpbuf[2][SN][CH / 4];  // [buf][s][chunk of 16 floats]
    __shared__ unsigned char ch[TN][32];     // choice bits: ch[j][lane] nibble of 4 rows
    __shared__ int dsh[SN];
    int b = blockIdx.x;
    int tid = threadIdx.x;
    const float* lp = out + BN * SN + ((size_t)b * SN) * TN;            // log_a_soft[b]
    float* hard = out + BN * SN + (size_t)BN * SN * TN + ((size_t)b * SN) * TN;
    float* dout = out + (size_t)b * SN;
    dsh[tid] = 0;
    // preload chunk 0 (thread tid owns row s=tid)
    {
        const float4* src = reinterpret_cast<const float4*>(lp + (size_t)tid * TN);
#pragma unroll
        for (int q = 0; q < 4; ++q) lpbuf[0][tid][q] = src[q];
    }
    __syncthreads();
    int ln = tid & 31, wid = tid >> 5;
    float q0 = NEGV, q1 = NEGV, q2 = NEGV, q3 = NEGV;
    const int NCH = TN / CH;  // 32 chunks
    for (int c = 0; c < NCH; ++c) {
        if (c + 1 < NCH) {  // prefetch next chunk into the other buffer
            const float4* src = reinterpret_cast<const float4*>(lp + (size_t)tid * TN + (c + 1) * CH);
            float4* dst = &lpbuf[(c + 1) & 1][tid][0];
#pragma unroll
            for (int q = 0; q < 4; ++q) dst[q] = src[q];
        }
        if (wid == 0) {
            const float* L = reinterpret_cast<const float*>(&lpbuf[c & 1][0][0]);  // [s][16]
#pragma unroll 4
            for (int jj = 0; jj < CH; ++jj) {
                int j = c * CH + jj;
                if (j == 0) {
                    q0 = (ln == 0) ? L[0 * CH + 0] : NEGV;
                    q1 = NEGV; q2 = NEGV; q3 = NEGV;
                    ch[0][ln] = 0;
                } else {
                    float up = __shfl_up_sync(0xffffffffu, q3, 1);
                    float s0 = (ln == 0) ? NEGV : up;
                    unsigned bits = 0;
                    bits |= (unsigned)(s0 >= q0);
                    bits |= ((unsigned)(q0 >= q1)) << 1;
                    bits |= ((unsigned)(q1 >= q2)) << 2;
                    bits |= ((unsigned)(q2 >= q3)) << 3;
                    float n0 = L[(4 * ln + 0) * CH + jj] + fmaxf(q0, s0);
                    float n1 = L[(4 * ln + 1) * CH + jj] + fmaxf(q1, q0);
                    float n2 = L[(4 * ln + 2) * CH + jj] + fmaxf(q2, q1);
                    float n3 = L[(4 * ln + 3) * CH + jj] + fmaxf(q3, q2);
                    q0 = n0; q1 = n1; q2 = n2; q3 = n3;
                    ch[j][ln] = (unsigned char)bits;
                }
            }
        }
        __syncthreads();
    }
    // backtrack (exact Glow-TTS semantics: mark current i, then step)
    if (tid == 0) {
        int i = tokl[b] - 1;
        int fl = featl[b];
        for (int j = TN - 1; j >= 0; --j) {
            if (j < fl) {
                hard[(size_t)i * TN + j] = 1.0f;
                dsh[i] += 1;
                int bit = (ch[j][i >> 2] >> (i & 3)) & 1;
                if (j > 0) i -= bit;
            }
        }
    }
    __syncthreads();
    dout[tid] = (float)dsh[tid];
}

// ---------------------------------------------------------------------------
// Launch
// ---------------------------------------------------------------------------
extern "C" void kernel_launch(void* const* d_in, const int* in_sizes, int n_in,
                              void* d_out, int out_size) {
    const float* h  = (const float*)d_in[0];
    const float* m  = (const float*)d_in[1];
    const int* tokl = (const int*)d_in[2];
    const int* fetl = (const int*)d_in[3];
    // d_in[4] = mask (recomputed from token_length inside dist kernel)
    const float* W1 = (const float*)d_in[5];
    const float* b1 = (const float*)d_in[6];
    const float* W2 = (const float*)d_in[7];
    const float* b2 = (const float*)d_in[8];
    const float* F1 = (const float*)d_in[9];
    const float* g1 = (const float*)d_in[10];
    const float* F2 = (const float*)d_in[11];
    const float* g2 = (const float*)d_in[12];
    const float* F3 = (const float*)d_in[13];
    const float* g3 = (const float*)d_in[14];
    float* out = (float*)d_out;

    const int ntr = DT * DT * 3 * 2 + DT * DT * 2 + DF * 3 * DT;  // 585728
    prep_weights_kernel<<<(ntr + 255) / 256, 256>>>(W1, W2, F1, F2, F3);
    text_conv_kernel<<<dim3(BN, SN / 16), 256>>>(h, b1, b2);
    feat_conv_kernel<<<dim3(BN, TN / 16), 256>>>(m, g1, g2, g3);
    dist_softmax_kernel<<<dim3(BN, TN / 32), 256>>>(tokl, out);
    mas_kernel<<<BN, 128>>>(tokl, fetl, out);
}

// round 2
// speedup vs baseline: 1.0020x; 1.0020x over previous
#include <cuda_runtime.h>
#include <math.h>

// Problem dims (fixed)
#define BN 8
#define SN 128
#define TN 512
#define DT 256
#define DF 80

#define NEGV (-1e9f)

// Scratch (static __device__ — no allocation allowed)
__device__ float g_ht[BN * SN * DT];   // text features after conv stack  (B,S,256)
__device__ float g_mt[BN * TN * DT];   // feat features after conv stack  (B,T,256)
__device__ float W1t[DT * 3 * DT];     // [(ci*3+k)][c]
__device__ float W2t[DT * DT];         // [ci][c]
__device__ float F1t[DF * 3 * DT];     // [(ci*3+k)][c]
__device__ float F2t[DT * 3 * DT];
__device__ float F3t[DT * DT];

// ---------------------------------------------------------------------------
// Weight transposition: make inner-loop weight reads coalesced over channel c.
// ---------------------------------------------------------------------------
__global__ void prep_weights_kernel(const float* __restrict__ W1, const float* __restrict__ W2,
                                    const float* __restrict__ F1, const float* __restrict__ F2,
                                    const float* __restrict__ F3) {
    int i = blockIdx.x * blockDim.x + threadIdx.x;
    const int n1 = DT * DT * 3;   // 196608
    const int n2 = DT * DT;       // 65536
    const int n3 = DF * 3 * DT;   // 61440
    const int n4 = DT * DT * 3;
    const int n5 = DT * DT;
    if (i < n1) { W1t[i] = W1[(i & 255) * (DT * 3) + (i >> 8)]; return; }
    i -= n1;
    if (i < n2) { W2t[i] = W2[(i & 255) * DT + (i >> 8)]; return; }
    i -= n2;
    if (i < n3) { F1t[i] = F1[(i & 255) * (DF * 3) + (i >> 8)]; return; }
    i -= n3;
    if (i < n4) { F2t[i] = F2[(i & 255) * (DT * 3) + (i >> 8)]; return; }
    i -= n4;
    if (i < n5) { F3t[i] = F3[(i & 255) * DT + (i >> 8)]; }
}

// ---------------------------------------------------------------------------
// Text path: conv3(W1)+b1 -> relu -> conv1(W2)+b2.  Tile: 16 positions/block.
// grid (B, S/16), 256 threads (one output channel each).
// ---------------------------------------------------------------------------
__global__ __launch_bounds__(256) void text_conv_kernel(const float* __restrict__ h,
                                                        const float* __restrict__ b1,
                                                        const float* __restrict__ b2) {
    const int TS = 16;
    __shared__ float sh_h[TS + 2][DT];     // input rows s0-1 .. s0+TS
    __shared__ float sh_y[DT][17];         // relu(conv1) transposed for stage 2
    int b = blockIdx.x, s0 = blockIdx.y * TS;
    int tid = threadIdx.x;   // = channel c
    // load input window (row s0-1+p), coalesced over channels
    for (int p = 0; p < TS + 2; ++p) {
        int s = s0 - 1 + p;
        float v = 0.f;
        if (s >= 0 && s < SN) v = h[((size_t)(b * SN + s)) * DT + tid];
        sh_h[p][tid] = v;
    }
    __syncthreads();
    int c = tid;
    float acc[TS];
    float bb = b1[c];
#pragma unroll
    for (int p = 0; p < TS; ++p) acc[p] = bb;
    for (int ci = 0; ci < DT; ++ci) {
#pragma unroll
        for (int k = 0; k < 3; ++k) {
            float w = W1t[(ci * 3 + k) * DT + c];
#pragma unroll
            for (int p = 0; p < TS; ++p) acc[p] = fmaf(w, sh_h[p + k][ci], acc[p]);
        }
    }
#pragma unroll
    for (int p = 0; p < TS; ++p) sh_y[c][p] = fmaxf(acc[p], 0.f);
    __syncthreads();
    float a2[TS];
    float bb2 = b2[c];
#pragma unroll
    for (int p = 0; p < TS; ++p) a2[p] = bb2;
    for (int ci = 0; ci < DT; ++ci) {
        float w = W2t[ci * DT + c];
#pragma unroll
        for (int p = 0; p < TS; ++p) a2[p] = fmaf(w, sh_y[ci][p], a2[p]);
    }
#pragma unroll
    for (int p = 0; p < TS; ++p)
        g_ht[((size_t)(b * SN + s0 + p)) * DT + c] = a2[p];
}

// ---------------------------------------------------------------------------
// Feat path: conv3(F1)+g1 -> relu -> conv3(F2)+g2 -> relu -> conv1(F3)+g3.
// Tile: 16 positions/block with halo.  grid (B, T/16), 256 threads.
// ---------------------------------------------------------------------------
__global__ __launch_bounds__(256) void feat_conv_kernel(const float* __restrict__ m,
                                                        const float* __restrict__ g1v,
                                                        const float* __restrict__ g2v,
                                                        const float* __restrict__ g3v) {
    const int TT = 16;
    __shared__ float sh_m[TT + 4][DF];   // m rows t0-2 .. t0+TT+1
    __shared__ float sh_a[DT][19];       // relu(y1), 18 positions (t0-1 .. t0+TT)
    __shared__ float sh_b[DT][17];       // relu(y2), 16 positions
    int b = blockIdx.x, t0 = blockIdx.y * TT;
    int tid = threadIdx.x;
    for (int idx = tid; idx < (TT + 4) * DF; idx += 256) {
        int p = idx / DF, ci = idx % DF;
        int t = t0 - 2 + p;
        sh_m[p][ci] = (t >= 0 && t < TN) ? m[((size_t)(b * TN + t)) * DF + ci] : 0.f;
    }
    __syncthreads();
    int c = tid;
    // stage 1: y1 over 18 positions (global t = t0-1+p)
    {
        float a1[TT + 2];
        float bb = g1v[c];
#pragma unroll
        for (int p = 0; p < TT + 2; ++p) a1[p] = bb;
        for (int ci = 0; ci < DF; ++ci) {
#pragma unroll
            for (int k = 0; k < 3; ++k) {
                float w = F1t[(ci * 3 + k) * DT + c];
#pragma unroll
                for (int p = 0; p < TT + 2; ++p) a1[p] = fmaf(w, sh_m[p + k][ci], a1[p]);
            }
        }
#pragma unroll
        for (int p = 0; p < TT + 2; ++p) sh_a[c][p] = fmaxf(a1[p], 0.f);
    }
    __syncthreads();
    // stage 2: y2 over 16 positions (global t = t0+p)
    {
        float a2[TT];
        float bb = g2v[c];
#pragma unroll
        for (int p = 0; p < TT; ++p) a2[p] = bb;
        for (int ci = 0; ci < DT; ++ci) {
#pragma unroll
            for (int k = 0; k < 3; ++k) {
                float w = F2t[(ci * 3 + k) * DT + c];
#pragma unroll
                for (int p = 0; p < TT; ++p) a2[p] = fmaf(w, sh_a[ci][p + k], a2[p]);
            }
        }
#pragma unroll
        for (int p = 0; p < TT; ++p) sh_b[c][p] = fmaxf(a2[p], 0.f);
    }
    __syncthreads();
    // stage 3: y3 = conv1
    {
        float a3[TT];
        float bb = g3v[c];
#pragma unroll
        for (int p = 0; p < TT; ++p) a3[p] = bb;
        for (int ci = 0; ci < DT; ++ci) {
            float w = F3t[ci * DT + c];
#pragma unroll
            for (int p = 0; p < TT; ++p) a3[p] = fmaf(w, sh_b[ci][p], a3[p]);
        }
#pragma unroll
        for (int p = 0; p < TT; ++p)
            g_mt[((size_t)(b * TN + t0 + p)) * DT + c] = a3[p];
    }
}

// ---------------------------------------------------------------------------
// Pairwise L2 distance + mask + log_softmax over S.  Tile: all 128 s x 32 t
// per block.  grid (B, T/32), 256 threads.  Also zeroes the a_hard region.
// ---------------------------------------------------------------------------
__global__ __launch_bounds__(256) void dist_softmax_kernel(const int* __restrict__ tokl,
                                                           float* __restrict__ out) {
    __shared__ float A[SN][33];
    __shared__ float Bm[32][33];
    __shared__ float Z[SN][33];
    __shared__ float mls[32];
    int b = blockIdx.x, t0 = blockIdx.y * 32;
    int tid = threadIdx.x;
    int ts = tid >> 3, tt = tid & 7;   // thread computes 4x4 microtile: s=4*ts+r, t=4*tt+j
    float acc[4][4];
#pragma unroll
    for (int r = 0; r < 4; ++r)
#pragma unroll
        for (int j = 0; j < 4; ++j) acc[r][j] = 0.f;

    for (int kc = 0; kc < DT / 32; ++kc) {
        int k0 = kc * 32;
        for (int idx = tid; idx < SN * 32; idx += 256) {
            int s = idx >> 5, kk = idx & 31;
            A[s][kk] = g_ht[((size_t)(b * SN + s)) * DT + k0 + kk];
        }
        for (int idx = tid; idx < 32 * 32; idx += 256) {
            int tl = idx >> 5, kk = idx & 31;
            Bm[tl][kk] = g_mt[((size_t)(b * TN + t0 + tl)) * DT + k0 + kk];
        }
        __syncthreads();
#pragma unroll 4
        for (int kk = 0; kk < 32; ++kk) {
            float av[4], bv[4];
#pragma unroll
            for (int r = 0; r < 4; ++r) av[r] = A[ts * 4 + r][kk];
#pragma unroll
            for (int j = 0; j < 4; ++j) bv[j] = Bm[tt * 4 + j][kk];
#pragma unroll
            for (int r = 0; r < 4; ++r)
#pragma unroll
                for (int j = 0; j < 4; ++j) {
                    float d = av[r] - bv[j];
                    acc[r][j] = fmaf(d, d, acc[r][j]);
                }
        }
        __syncthreads();
    }
    int tok = tokl[b];
#pragma unroll
    for (int r = 0; r < 4; ++r) {
        int s = ts * 4 + r;
        float dist;
#pragma unroll
        for (int j = 0; j < 4; ++j) {
            dist = (s < tok) ? sqrtf(fmaxf(acc[r][j], 0.f)) : 0.f;
            Z[s][tt * 4 + j] = -dist;
        }
    }
    __syncthreads();
    // column log-softmax over s: 8 threads per t-column (consecutive lanes)
    int tcol = tid >> 3, l = tid & 7;
    float mx = -3.4e38f;
#pragma unroll
    for (int i2 = 0; i2 < 16; ++i2) mx = fmaxf(mx, Z[l * 16 + i2][tcol]);
    mx = fmaxf(mx, __shfl_xor_sync(0xffffffffu, mx, 4));
    mx = fmaxf(mx, __shfl_xor_sync(0xffffffffu, mx, 2));
    mx = fmaxf(mx, __shfl_xor_sync(0xffffffffu, mx, 1));
    float sm = 0.f;
#pragma unroll
    for (int i2 = 0; i2 < 16; ++i2) sm += expf(Z[l * 16 + i2][tcol] - mx);
    sm += __shfl_xor_sync(0xffffffffu, sm, 4);
    sm += __shfl_xor_sync(0xffffffffu, sm, 2);
    sm += __shfl_xor_sync(0xffffffffu, sm, 1);
    if (l == 0) mls[tcol] = mx + logf(sm);
    __syncthreads();
    float* out_log = out + BN * SN;
    float* out_hard = out + BN * SN + (size_t)BN * SN * TN;
    for (int idx = tid; idx < SN * 32; idx += 256) {
        int s = idx >> 5, tl = idx & 31;
        size_t o = ((size_t)(b * SN + s)) * TN + t0 + tl;
        out_log[o] = Z[s][tl] - mls[tl];
        out_hard[o] = 0.f;   // zero-init a_hard (MAS writes the ones afterwards)
    }
}

// ---------------------------------------------------------------------------
// MAS: forward DP entirely inside warp 0 (4 rows/lane, shfl for s-1 neighbor);
// warps 0-3 cooperatively double-buffer log_a_soft columns into shared.
// Backtrack by thread 0.  grid (B), 128 threads.
// ---------------------------------------------------------------------------
__global__ __launch_bounds__(128) void mas_kernel(const int* __restrict__ tokl,
                                                  const int* __restrict__ featl,
                                                  float* __restrict__ out) {
    const int CH = 16;                       // j-columns per chunk
    __shared__ float4 lpbuf[2][SN][CH / 4];  // [buf][s][chunk of 16 floats]
    __shared__ unsigned char ch[TN][32];     // choice bits: ch[j][lane] nibble of 4 rows
    __shared__ int dsh[SN];
    int b = blockIdx.x;
    int tid = threadIdx.x;
    const float* lp = out + BN * SN + ((size_t)b * SN) * TN;            // log_a_soft[b]
    float* hard = out + BN * SN + (size_t)BN * SN * TN + ((size_t)b * SN) * TN;
    float* dout = out + (size_t)b * SN;
    dsh[tid] = 0;
    // preload chunk 0 (thread tid owns row s=tid)
    {
        const float4* src = reinterpret_cast<const float4*>(lp + (size_t)tid * TN);
#pragma unroll
        for (int q = 0; q < 4; ++q) lpbuf[0][tid][q] = src[q];
    }
    __syncthreads();
    int ln = tid & 31, wid = tid >> 5;
    float q0 = NEGV, q1 = NEGV, q2 = NEGV, q3 = NEGV;
    const int NCH = TN / CH;  // 32 chunks
    for (int c = 0; c < NCH; ++c) {
        if (c + 1 < NCH) {  // prefetch next chunk into the other buffer
            const float4* src = reinterpret_cast<const float4*>(lp + (size_t)tid * TN + (c + 1) * CH);
            float4* dst = &lpbuf[(c + 1) & 1][tid][0];
#pragma unroll
            for (int q = 0; q < 4; ++q) dst[q] = src[q];
        }
        if (wid == 0) {
            const float* L = reinterpret_cast<const float*>(&lpbuf[c & 1][0][0]);  // [s][16]
#pragma unroll 4
            for (int jj = 0; jj < CH; ++jj) {
                int j = c * CH + jj;
                if (j == 0) {
                    q0 = (ln == 0) ? L[0 * CH + 0] : NEGV;
                    q1 = NEGV; q2 = NEGV; q3 = NEGV;
                    ch[0][ln] = 0;
                } else {
                    float up = __shfl_up_sync(0xffffffffu, q3, 1);
                    float s0 = (ln == 0) ? NEGV : up;
                    unsigned bits = 0;
                    bits |= (unsigned)(s0 >= q0);
                    bits |= ((unsigned)(q0 >= q1)) << 1;
                    bits |= ((unsigned)(q1 >= q2)) << 2;
                    bits |= ((unsigned)(q2 >= q3)) << 3;
                    float n0 = L[(4 * ln + 0) * CH + jj] + fmaxf(q0, s0);
                    float n1 = L[(4 * ln + 1) * CH + jj] + fmaxf(q1, q0);
                    float n2 = L[(4 * ln + 2) * CH + jj] + fmaxf(q2, q1);
                    float n3 = L[(4 * ln + 3) * CH + jj] + fmaxf(q3, q2);
                    q0 = n0; q1 = n1; q2 = n2; q3 = n3;
                    ch[j][ln] = (unsigned char)bits;
                }
            }
        }
        __syncthreads();
    }
    // backtrack (exact Glow-TTS semantics: mark current i, then step)
    if (tid == 0) {
        int i = tokl[b] - 1;
        int fl = featl[b];
        for (int j = TN - 1; j >= 0; --j) {
            if (j < fl) {
                hard[(size_t)i * TN + j] = 1.0f;
                dsh[i] += 1;
                int bit = (ch[j][i >> 2] >> (i & 3)) & 1;
                if (j > 0) i -= bit;
            }
        }
    }
    __syncthreads();
    dout[tid] = (float)dsh[tid];
}

// ---------------------------------------------------------------------------
// Launch
// ---------------------------------------------------------------------------
extern "C" void kernel_launch(void* const* d_in, const int* in_sizes, int n_in,
                              void* d_out, int out_size) {
    const float* h  = (const float*)d_in[0];
    const float* m  = (const float*)d_in[1];
    const int* tokl = (const int*)d_in[2];
    const int* fetl = (const int*)d_in[3];
    // d_in[4] = mask (recomputed from token_length inside dist kernel)
    const float* W1 = (const float*)d_in[5];
    const float* b1 = (const float*)d_in[6];
    const float* W2 = (const float*)d_in[7];
    const float* b2 = (const float*)d_in[8];
    const float* F1 = (const float*)d_in[9];
    const float* g1 = (const float*)d_in[10];
    const float* F2 = (const float*)d_in[11];
    const float* g2 = (const float*)d_in[12];
    const float* F3 = (const float*)d_in[13];
    const float* g3 = (const float*)d_in[14];
    float* out = (float*)d_out;

    const int ntr = DT * DT * 3 * 2 + DT * DT * 2 + DF * 3 * DT;  // 585728
    prep_weights_kernel<<<(ntr + 255) / 256, 256>>>(W1, W2, F1, F2, F3);
    text_conv_kernel<<<dim3(BN, SN / 16), 256>>>(h, b1, b2);
    feat_conv_kernel<<<dim3(BN, TN / 16), 256>>>(m, g1, g2, g3);
    dist_softmax_kernel<<<dim3(BN, TN / 32), 256>>>(tokl, out);
    mas_kernel<<<BN, 128>>>(tokl, fetl, out);
}

// round 3
// speedup vs baseline: 1.3376x; 1.3349x over previous
#include <cuda_runtime.h>
#include <math.h>

#define BN 8
#define SN 128
#define TN 512
#define DT 256
#define DF 80
#define NEGV (-1e9f)

typedef unsigned long long ull;

__device__ float g_ht[BN * SN * DT];
__device__ float g_mt[BN * TN * DT];
__device__ float W1t[768 * DT];
__device__ float W2t[DT * DT];
__device__ float F1t[240 * DT];
__device__ float F2t[768 * DT];
__device__ float F3t[DT * DT];

__device__ __forceinline__ ull pk2(float lo, float hi) {
    ull r; asm("mov.b64 %0,{%1,%2};" : "=l"(r) : "f"(lo), "f"(hi)); return r;
}
__device__ __forceinline__ void upk2(ull v, float& lo, float& hi) {
    asm("mov.b64 {%0,%1},%2;" : "=f"(lo), "=f"(hi) : "l"(v));
}
__device__ __forceinline__ ull fma2(ull a, ull b, ull c) {
    ull d; asm("fma.rn.f32x2 %0,%1,%2,%3;" : "=l"(d) : "l"(a), "l"(b), "l"(c)); return d;
}
__device__ __forceinline__ ull add2(ull a, ull b) {
    ull d; asm("add.rn.f32x2 %0,%1,%2;" : "=l"(d) : "l"(a), "l"(b)); return d;
}
__device__ __forceinline__ ull ld64s(const float* p) { return *reinterpret_cast<const ull*>(p); }

// --------------------------------------------------------------------------
// Coalesced weight transposes (all matrices have 256 rows = out-channels).
// --------------------------------------------------------------------------
__global__ __launch_bounds__(256) void transpose_kernel(const float* __restrict__ W1,
                                                        const float* __restrict__ W2,
                                                        const float* __restrict__ F1,
                                                        const float* __restrict__ F2,
                                                        const float* __restrict__ F3) {
    __shared__ float tile[32][33];
    int blk = blockIdx.x;
    const float* src; float* dst; int C; int t;
    if (blk < 192)      { src = W1; dst = W1t; C = 768; t = blk; }
    else if (blk < 256) { src = W2; dst = W2t; C = 256; t = blk - 192; }
    else if (blk < 320) { src = F1; dst = F1t; C = 240; t = blk - 256; }
    else if (blk < 512) { src = F2; dst = F2t; C = 768; t = blk - 320; }
    else                { src = F3; dst = F3t; C = 256; t = blk - 512; }
    int Ct = (C + 31) >> 5;
    int tr = t / Ct, tc = t - tr * Ct;
    int tx = threadIdx.x & 31, ty = threadIdx.x >> 5;
#pragma unroll
    for (int i = 0; i < 4; ++i) {
        int r = tr * 32 + ty + i * 8, cc = tc * 32 + tx;
        tile[ty + i * 8][tx] = (cc < C) ? src[(size_t)r * C + cc] : 0.f;
    }
    __syncthreads();
#pragma unroll
    for (int i = 0; i < 4; ++i) {
        int cc = tc * 32 + ty + i * 8, r = tr * 32 + tx;
        if (cc < C) dst[(size_t)cc * 256 + r] = tile[tx][ty + i * 8];
    }
}

// --------------------------------------------------------------------------
// Packed conv helpers.  Per-element accumulation order == R1 (bias, then ci
// ascending, k 0..2 within ci) -> bitwise-identical results.
// --------------------------------------------------------------------------
template <int NC, int RS, int NP>
__device__ __forceinline__ void conv3pairs(const float* src, const float* wt, float bias, ull* acc) {
    ull bb = pk2(bias, bias);
#pragma unroll
    for (int i = 0; i < NP; ++i) acc[i] = bb;
    for (int ci = 0; ci < NC; ++ci) {
        const float* x = src + ci * RS;
        ull P[NP + 1];
#pragma unroll
        for (int i = 0; i <= NP; ++i) P[i] = ld64s(x + 2 * i);
        float lo[NP + 1], hi[NP + 1];
#pragma unroll
        for (int i = 0; i <= NP; ++i) upk2(P[i], lo[i], hi[i]);
        ull O[NP];
#pragma unroll
        for (int i = 0; i < NP; ++i) O[i] = pk2(hi[i], lo[i + 1]);
        const float* wp = wt + ci * 3 * DT;
        ull w0 = pk2(wp[0], wp[0]), w1 = pk2(wp[DT], wp[DT]), w2 = pk2(wp[2 * DT], wp[2 * DT]);
#pragma unroll
        for (int i = 0; i < NP; ++i) acc[i] = fma2(w0, P[i], acc[i]);
#pragma unroll
        for (int i = 0; i < NP; ++i) acc[i] = fma2(w1, O[i], acc[i]);
#pragma unroll
        for (int i = 0; i < NP; ++i) acc[i] = fma2(w2, P[i + 1], acc[i]);
    }
}

template <int NP>
__device__ __forceinline__ void conv1pairs(const float* src, int RS, const float* wt, float bias, ull* acc) {
    ull bb = pk2(bias, bias);
#pragma unroll
    for (int i = 0; i < NP; ++i) acc[i] = bb;
    for (int ci = 0; ci < DT; ++ci) {
        const float* x = src + ci * RS;
        float w = wt[ci * DT];
        ull wpk = pk2(w, w);
#pragma unroll
        for (int i = 0; i < NP; ++i) acc[i] = fma2(wpk, ld64s(x + 2 * i), acc[i]);
    }
}

// --------------------------------------------------------------------------
// Fused conv: blocks [0,256) feat path (b x 32 tiles of 16 t),
// blocks [256,320) text path (b x 8 tiles of 16 s).  256 threads = channel.
// --------------------------------------------------------------------------
__global__ __launch_bounds__(256) void conv_all_kernel(const float* __restrict__ h,
                                                       const float* __restrict__ m,
                                                       const float* __restrict__ b1v,
                                                       const float* __restrict__ b2v,
                                                       const float* __restrict__ g1v,
                                                       const float* __restrict__ g2v,
                                                       const float* __restrict__ g3v) {
    __shared__ __align__(16) float sbuf[10304];
    int tid = threadIdx.x, blk = blockIdx.x, c = tid;
    if (blk < 256) {
        float* mT = sbuf;            // [80][20]  t0-2 .. t0+17
        float* A0 = sbuf + 1600;     // [256][18] y1 at t0-1 .. t0+16
        float* B0 = sbuf + 6208;     // [256][16] y2 at t0 .. t0+15
        int b = blk >> 5, t0 = (blk & 31) << 4;
        for (int idx = tid; idx < 1600; idx += 256) {
            int p = idx / 80, ci = idx - p * 80;
            int t = t0 - 2 + p;
            mT[ci * 20 + p] = (t >= 0 && t < TN) ? m[((size_t)(b * TN + t)) * DF + ci] : 0.f;
        }
        __syncthreads();
        {
            ull acc[9];
            conv3pairs<DF, 20, 9>(mT, F1t + c, g1v[c], acc);
#pragma unroll
            for (int i = 0; i < 9; ++i) {
                float v0, v1; upk2(acc[i], v0, v1);
                int g = t0 - 1 + 2 * i;
                A0[c * 18 + 2 * i] = (g >= 0 && g < TN) ? fmaxf(v0, 0.f) : 0.f;
                ++g;
                A0[c * 18 + 2 * i + 1] = (g >= 0 && g < TN) ? fmaxf(v1, 0.f) : 0.f;
            }
        }
        __syncthreads();
        {
            ull acc[8];
            conv3pairs<DT, 18, 8>(A0, F2t + c, g2v[c], acc);
#pragma unroll
            for (int i = 0; i < 8; ++i) {
                float v0, v1; upk2(acc[i], v0, v1);
                B0[c * 16 + 2 * i] = fmaxf(v0, 0.f);
                B0[c * 16 + 2 * i + 1] = fmaxf(v1, 0.f);
            }
        }
        __syncthreads();
        {
            ull acc[8];
            conv1pairs<8>(B0, 16, F3t + c, g3v[c], acc);
#pragma unroll
            for (int i = 0; i < 8; ++i) {
                float v0, v1; upk2(acc[i], v0, v1);
                g_mt[((size_t)(b * TN + t0 + 2 * i)) * DT + c] = v0;
                g_mt[((size_t)(b * TN + t0 + 2 * i + 1)) * DT + c] = v1;
            }
        }
    } else {
        float* hT = sbuf;            // [256][18]  s0-1 .. s0+16
        float* yT = sbuf + 4608;     // [256][16]
        int q = blk - 256;
        int b = q >> 3, s0 = (q & 7) << 4;
        for (int idx = tid; idx < 4608; idx += 256) {
            int p = idx >> 8, cc = idx & 255;
            int s = s0 - 1 + p;
            hT[cc * 18 + p] = (s >= 0 && s < SN) ? h[((size_t)(b * SN + s)) * DT + cc] : 0.f;
        }
        __syncthreads();
        {
            ull acc[8];
            conv3pairs<DT, 18, 8>(hT, W1t + c, b1v[c], acc);
#pragma unroll
            for (int i = 0; i < 8; ++i) {
                float v0, v1; upk2(acc[i], v0, v1);
                yT[c * 16 + 2 * i] = fmaxf(v0, 0.f);
                yT[c * 16 + 2 * i + 1] = fmaxf(v1, 0.f);
            }
        }
        __syncthreads();
        {
            ull acc[8];
            conv1pairs<8>(yT, 16, W2t + c, b2v[c], acc);
#pragma unroll
            for (int i = 0; i < 8; ++i) {
                float v0, v1; upk2(acc[i], v0, v1);
                g_ht[((size_t)(b * SN + s0 + 2 * i)) * DT + c] = v0;
                g_ht[((size_t)(b * SN + s0 + 2 * i + 1)) * DT + c] = v1;
            }
        }
    }
}

// --------------------------------------------------------------------------
// L2 distance + mask + log_softmax over S.  grid (8,32), 128 threads,
// 16 t-cols per block, 4x4 microtile, packed f32x2, sequential k order.
// --------------------------------------------------------------------------
__global__ __launch_bounds__(128) void dist_softmax_kernel(const int* __restrict__ tokl,
                                                           float* __restrict__ out) {
    __shared__ float A[SN][33];
    __shared__ __align__(8) float Bs[32][18];   // negated, [kk][t]
    __shared__ float Z[SN][17];
    __shared__ float mls[16];
    int b = blockIdx.x, t0 = blockIdx.y * 16;
    int tid = threadIdx.x;
    int ts = tid >> 2, tt = tid & 3;
    ull acc[4][2];
#pragma unroll
    for (int r = 0; r < 4; ++r) { acc[r][0] = 0ULL; acc[r][1] = 0ULL; }
    for (int cch = 0; cch < 8; ++cch) {
        int k0 = cch * 32;
        for (int idx = tid; idx < SN * 32; idx += 128) {
            int s = idx >> 5, kk = idx & 31;
            A[s][kk] = g_ht[((size_t)(b * SN + s)) * DT + k0 + kk];
        }
        for (int idx = tid; idx < 16 * 32; idx += 128) {
            int t = idx >> 5, kk = idx & 31;
            Bs[kk][t] = -g_mt[((size_t)(b * TN + t0 + t)) * DT + k0 + kk];
        }
        __syncthreads();
#pragma unroll 4
        for (int kk = 0; kk < 32; ++kk) {
            ull bq0 = ld64s(&Bs[kk][tt * 4]);
            ull bq1 = ld64s(&Bs[kk][tt * 4 + 2]);
#pragma unroll
            for (int r = 0; r < 4; ++r) {
                float av = A[ts * 4 + r][kk];
                ull ap = pk2(av, av);
                ull d0 = add2(ap, bq0);
                acc[r][0] = fma2(d0, d0, acc[r][0]);
                ull d1 = add2(ap, bq1);
                acc[r][1] = fma2(d1, d1, acc[r][1]);
            }
        }
        __syncthreads();
    }
    int tok = tokl[b];
#pragma unroll
    for (int r = 0; r < 4; ++r) {
        int s = ts * 4 + r;
        float v[4];
        upk2(acc[r][0], v[0], v[1]);
        upk2(acc[r][1], v[2], v[3]);
#pragma unroll
        for (int j = 0; j < 4; ++j) {
            float dd = (s < tok) ? sqrtf(fmaxf(v[j], 0.f)) : 0.f;
            Z[s][tt * 4 + j] = -dd;
        }
    }
    __syncthreads();
    int tcol = tid >> 3, l = tid & 7;
    float mx = -3.4e38f;
#pragma unroll
    for (int i2 = 0; i2 < 16; ++i2) mx = fmaxf(mx, Z[l * 16 + i2][tcol]);
    mx = fmaxf(mx, __shfl_xor_sync(0xffffffffu, mx, 4));
    mx = fmaxf(mx, __shfl_xor_sync(0xffffffffu, mx, 2));
    mx = fmaxf(mx, __shfl_xor_sync(0xffffffffu, mx, 1));
    float sm = 0.f;
#pragma unroll
    for (int i2 = 0; i2 < 16; ++i2) sm += expf(Z[l * 16 + i2][tcol] - mx);
    sm += __shfl_xor_sync(0xffffffffu, sm, 4);
    sm += __shfl_xor_sync(0xffffffffu, sm, 2);
    sm += __shfl_xor_sync(0xffffffffu, sm, 1);
    if (l == 0) mls[tcol] = mx + logf(sm);
    __syncthreads();
    float* out_log = out + BN * SN;
    float* out_hard = out + BN * SN + (size_t)BN * SN * TN;
    for (int idx = tid; idx < SN * 16; idx += 128) {
        int s = idx >> 4, tl = idx & 15;
        size_t o = ((size_t)(b * SN + s)) * TN + t0 + tl;
        out_log[o] = Z[s][tl] - mls[tl];
        out_hard[o] = 0.f;
    }
}

// --------------------------------------------------------------------------
// MAS (identical to the passing R1 version).
// --------------------------------------------------------------------------
__global__ __launch_bounds__(128) void mas_kernel(const int* __restrict__ tokl,
                                                  const int* __restrict__ featl,
                                                  float* __restrict__ out) {
    const int CH = 16;
    __shared__ float4 lpbuf[2][SN][CH / 4];
    __shared__ unsigned char ch[TN][32];
    __shared__ int dsh[SN];
    int b = blockIdx.x;
    int tid = threadIdx.x;
    const float* lp = out + BN * SN + ((size_t)b * SN) * TN;
    float* hard = out + BN * SN + (size_t)BN * SN * TN + ((size_t)b * SN) * TN;
    float* dout = out + (size_t)b * SN;
    dsh[tid] = 0;
    {
        const float4* src = reinterpret_cast<const float4*>(lp + (size_t)tid * TN);
#pragma unroll
        for (int q = 0; q < 4; ++q) lpbuf[0][tid][q] = src[q];
    }
    __syncthreads();
    int ln = tid & 31, wid = tid >> 5;
    float q0 = NEGV, q1 = NEGV, q2 = NEGV, q3 = NEGV;
    const int NCH = TN / CH;
    for (int c = 0; c < NCH; ++c) {
        if (c + 1 < NCH) {
            const float4* src = reinterpret_cast<const float4*>(lp + (size_t)tid * TN + (c + 1) * CH);
            float4* dst = &lpbuf[(c + 1) & 1][tid][0];
#pragma unroll
            for (int q = 0; q < 4; ++q) dst[q] = src[q];
        }
        if (wid == 0) {
            const float* L = reinterpret_cast<const float*>(&lpbuf[c & 1][0][0]);
#pragma unroll 4
            for (int jj = 0; jj < CH; ++jj) {
                int j = c * CH + jj;
                if (j == 0) {
                    q0 = (ln == 0) ? L[0] : NEGV;
                    q1 = NEGV; q2 = NEGV; q3 = NEGV;
                    ch[0][ln] = 0;
                } else {
                    float up = __shfl_up_sync(0xffffffffu, q3, 1);
                    float s0 = (ln == 0) ? NEGV : up;
                    unsigned bits = 0;
                    bits |= (unsigned)(s0 >= q0);
                    bits |= ((unsigned)(q0 >= q1)) << 1;
                    bits |= ((unsigned)(q1 >= q2)) << 2;
                    bits |= ((unsigned)(q2 >= q3)) << 3;
                    float n0 = L[(4 * ln + 0) * CH + jj] + fmaxf(q0, s0);
                    float n1 = L[(4 * ln + 1) * CH + jj] + fmaxf(q1, q0);
                    float n2 = L[(4 * ln + 2) * CH + jj] + fmaxf(q2, q1);
                    float n3 = L[(4 * ln + 3) * CH + jj] + fmaxf(q3, q2);
                    q0 = n0; q1 = n1; q2 = n2; q3 = n3;
                    ch[j][ln] = (unsigned char)bits;
                }
            }
        }
        __syncthreads();
    }
    if (tid == 0) {
        int i = tokl[b] - 1;
        int fl = featl[b];
        for (int j = TN - 1; j >= 0; --j) {
            if (j < fl) {
                hard[(size_t)i * TN + j] = 1.0f;
                dsh[i] += 1;
                int bit = (ch[j][i >> 2] >> (i & 3)) & 1;
                if (j > 0) i -= bit;
            }
        }
    }
    __syncthreads();
    dout[tid] = (float)dsh[tid];
}

extern "C" void kernel_launch(void* const* d_in, const int* in_sizes, int n_in,
                              void* d_out, int out_size) {
    const float* h  = (const float*)d_in[0];
    const float* m  = (const float*)d_in[1];
    const int* tokl = (const int*)d_in[2];
    const int* fetl = (const int*)d_in[3];
    const float* W1 = (const float*)d_in[5];
    const float* b1 = (const float*)d_in[6];
    const float* W2 = (const float*)d_in[7];
    const float* b2 = (const float*)d_in[8];
    const float* F1 = (const float*)d_in[9];
    const float* g1 = (const float*)d_in[10];
    const float* F2 = (const float*)d_in[11];
    const float* g2 = (const float*)d_in[12];
    const float* F3 = (const float*)d_in[13];
    const float* g3 = (const float*)d_in[14];
    float* out = (float*)d_out;

    transpose_kernel<<<576, 256>>>(W1, W2, F1, F2, F3);
    conv_all_kernel<<<320, 256>>>(h, m, b1, b2, g1, g2, g3);
    dist_softmax_kernel<<<dim3(BN, TN / 16), 128>>>(tokl, out);
    mas_kernel<<<BN, 128>>>(tokl, fetl, out);
}

// round 5
// speedup vs baseline: 1.7786x; 1.3297x over previous
#include <cuda_runtime.h>
#include <math.h>

#define BN 8
#define SN 128
#define TN 512
#define DT 256
#define DF 80
#define NEGV (-1e9f)

typedef unsigned long long ull;

__device__ float g_ht[BN * SN * DT];
__device__ float g_mt[BN * TN * DT];
__device__ float g_lpT[BN * TN * SN];   // transposed log_a_soft [b][t][s]
__device__ float W1t[768 * DT];
__device__ float W2t[DT * DT];
__device__ float F1t[240 * DT];
__device__ float F2t[768 * DT];
__device__ float F3t[DT * DT];

__device__ __forceinline__ ull pk2(float lo, float hi) {
    ull r; asm("mov.b64 %0,{%1,%2};" : "=l"(r) : "f"(lo), "f"(hi)); return r;
}
__device__ __forceinline__ void upk2(ull v, float& lo, float& hi) {
    asm("mov.b64 {%0,%1},%2;" : "=f"(lo), "=f"(hi) : "l"(v));
}
__device__ __forceinline__ ull fma2(ull a, ull b, ull c) {
    ull d; asm("fma.rn.f32x2 %0,%1,%2,%3;" : "=l"(d) : "l"(a), "l"(b), "l"(c)); return d;
}
__device__ __forceinline__ ull add2(ull a, ull b) {
    ull d; asm("add.rn.f32x2 %0,%1,%2;" : "=l"(d) : "l"(a), "l"(b)); return d;
}
__device__ __forceinline__ ull ld64s(const float* p) { return *reinterpret_cast<const ull*>(p); }

// --------------------------------------------------------------------------
// Coalesced weight transposes.
// --------------------------------------------------------------------------
__global__ __launch_bounds__(256) void transpose_kernel(const float* __restrict__ W1,
                                                        const float* __restrict__ W2,
                                                        const float* __restrict__ F1,
                                                        const float* __restrict__ F2,
                                                        const float* __restrict__ F3) {
    __shared__ float tile[32][33];
    int blk = blockIdx.x;
    const float* src; float* dst; int C; int t;
    if (blk < 192)      { src = W1; dst = W1t; C = 768; t = blk; }
    else if (blk < 256) { src = W2; dst = W2t; C = 256; t = blk - 192; }
    else if (blk < 320) { src = F1; dst = F1t; C = 240; t = blk - 256; }
    else if (blk < 512) { src = F2; dst = F2t; C = 768; t = blk - 320; }
    else                { src = F3; dst = F3t; C = 256; t = blk - 512; }
    int Ct = (C + 31) >> 5;
    int tr = t / Ct, tc = t - tr * Ct;
    int tx = threadIdx.x & 31, ty = threadIdx.x >> 5;
#pragma unroll
    for (int i = 0; i < 4; ++i) {
        int r = tr * 32 + ty + i * 8, cc = tc * 32 + tx;
        tile[ty + i * 8][tx] = (cc < C) ? src[(size_t)r * C + cc] : 0.f;
    }
    __syncthreads();
#pragma unroll
    for (int i = 0; i < 4; ++i) {
        int cc = tc * 32 + ty + i * 8, r = tr * 32 + tx;
        if (cc < C) dst[(size_t)cc * 256 + r] = tile[tx][ty + i * 8];
    }
}

// --------------------------------------------------------------------------
// Packed conv helpers (identical math to R3).
// --------------------------------------------------------------------------
template <int NC, int RS, int NP>
__device__ __forceinline__ void conv3pairs(const float* src, const float* wt, float bias, ull* acc) {
    ull bb = pk2(bias, bias);
#pragma unroll
    for (int i = 0; i < NP; ++i) acc[i] = bb;
    for (int ci = 0; ci < NC; ++ci) {
        const float* x = src + ci * RS;
        ull P[NP + 1];
#pragma unroll
        for (int i = 0; i <= NP; ++i) P[i] = ld64s(x + 2 * i);
        float lo[NP + 1], hi[NP + 1];
#pragma unroll
        for (int i = 0; i <= NP; ++i) upk2(P[i], lo[i], hi[i]);
        ull O[NP];
#pragma unroll
        for (int i = 0; i < NP; ++i) O[i] = pk2(hi[i], lo[i + 1]);
        const float* wp = wt + ci * 3 * DT;
        ull w0 = pk2(wp[0], wp[0]), w1 = pk2(wp[DT], wp[DT]), w2 = pk2(wp[2 * DT], wp[2 * DT]);
#pragma unroll
        for (int i = 0; i < NP; ++i) acc[i] = fma2(w0, P[i], acc[i]);
#pragma unroll
        for (int i = 0; i < NP; ++i) acc[i] = fma2(w1, O[i], acc[i]);
#pragma unroll
        for (int i = 0; i < NP; ++i) acc[i] = fma2(w2, P[i + 1], acc[i]);
    }
}

template <int NP>
__device__ __forceinline__ void conv1pairs(const float* src, int RS, const float* wt, float bias, ull* acc) {
    ull bb = pk2(bias, bias);
#pragma unroll
    for (int i = 0; i < NP; ++i) acc[i] = bb;
    for (int ci = 0; ci < DT; ++ci) {
        const float* x = src + ci * RS;
        float w = wt[ci * DT];
        ull wpk = pk2(w, w);
#pragma unroll
        for (int i = 0; i < NP; ++i) acc[i] = fma2(wpk, ld64s(x + 2 * i), acc[i]);
    }
}

// --------------------------------------------------------------------------
// Fused conv: blocks [0,256) feat path, [256,320) text path.  256 thr = chan.
// --------------------------------------------------------------------------
__global__ __launch_bounds__(256) void conv_all_kernel(const float* __restrict__ h,
                                                       const float* __restrict__ m,
                                                       const float* __restrict__ b1v,
                                                       const float* __restrict__ b2v,
                                                       const float* __restrict__ g1v,
                                                       const float* __restrict__ g2v,
                                                       const float* __restrict__ g3v) {
    __shared__ __align__(16) float sbuf[10304];
    int tid = threadIdx.x, blk = blockIdx.x, c = tid;
    if (blk < 256) {
        float* mT = sbuf;            // [80][20]
        float* A0 = sbuf + 1600;     // [256][18]
        float* B0 = sbuf + 6208;     // [256][16]
        int b = blk >> 5, t0 = (blk & 31) << 4;
        for (int idx = tid; idx < 1600; idx += 256) {
            int p = idx / 80, ci = idx - p * 80;
            int t = t0 - 2 + p;
            mT[ci * 20 + p] = (t >= 0 && t < TN) ? m[((size_t)(b * TN + t)) * DF + ci] : 0.f;
        }
        __syncthreads();
        {
            ull acc[9];
            conv3pairs<DF, 20, 9>(mT, F1t + c, g1v[c], acc);
#pragma unroll
            for (int i = 0; i < 9; ++i) {
                float v0, v1; upk2(acc[i], v0, v1);
                int g = t0 - 1 + 2 * i;
                A0[c * 18 + 2 * i] = (g >= 0 && g < TN) ? fmaxf(v0, 0.f) : 0.f;
                ++g;
                A0[c * 18 + 2 * i + 1] = (g >= 0 && g < TN) ? fmaxf(v1, 0.f) : 0.f;
            }
        }
        __syncthreads();
        {
            ull acc[8];
            conv3pairs<DT, 18, 8>(A0, F2t + c, g2v[c], acc);
#pragma unroll
            for (int i = 0; i < 8; ++i) {
                float v0, v1; upk2(acc[i], v0, v1);
                B0[c * 16 + 2 * i] = fmaxf(v0, 0.f);
                B0[c * 16 + 2 * i + 1] = fmaxf(v1, 0.f);
            }
        }
        __syncthreads();
        {
            ull acc[8];
            conv1pairs<8>(B0, 16, F3t + c, g3v[c], acc);
#pragma unroll
            for (int i = 0; i < 8; ++i) {
                float v0, v1; upk2(acc[i], v0, v1);
                g_mt[((size_t)(b * TN + t0 + 2 * i)) * DT + c] = v0;
                g_mt[((size_t)(b * TN + t0 + 2 * i + 1)) * DT + c] = v1;
            }
        }
    } else {
        float* hT = sbuf;            // [256][18]
        float* yT = sbuf + 4608;     // [256][16]
        int q = blk - 256;
        int b = q >> 3, s0 = (q & 7) << 4;
        for (int idx = tid; idx < 4608; idx += 256) {
            int p = idx >> 8, cc = idx & 255;
            int s = s0 - 1 + p;
            hT[cc * 18 + p] = (s >= 0 && s < SN) ? h[((size_t)(b * SN + s)) * DT + cc] : 0.f;
        }
        __syncthreads();
        {
            ull acc[8];
            conv3pairs<DT, 18, 8>(hT, W1t + c, b1v[c], acc);
#pragma unroll
            for (int i = 0; i < 8; ++i) {
                float v0, v1; upk2(acc[i], v0, v1);
                yT[c * 16 + 2 * i] = fmaxf(v0, 0.f);
                yT[c * 16 + 2 * i + 1] = fmaxf(v1, 0.f);
            }
        }
        __syncthreads();
        {
            ull acc[8];
            conv1pairs<8>(yT, 16, W2t + c, b2v[c], acc);
#pragma unroll
            for (int i = 0; i < 8; ++i) {
                float v0, v1; upk2(acc[i], v0, v1);
                g_ht[((size_t)(b * SN + s0 + 2 * i)) * DT + c] = v0;
                g_ht[((size_t)(b * SN + s0 + 2 * i + 1)) * DT + c] = v1;
            }
        }
    }
}

// --------------------------------------------------------------------------
// L2 distance + log_softmax (same math as R3) + transposed side-output g_lpT.
// --------------------------------------------------------------------------
__global__ __launch_bounds__(128) void dist_softmax_kernel(const int* __restrict__ tokl,
                                                           float* __restrict__ out) {
    __shared__ float A[SN][33];
    __shared__ __align__(8) float Bs[32][18];
    __shared__ float Z[SN][17];
    __shared__ float mls[16];
    int b = blockIdx.x, t0 = blockIdx.y * 16;
    int tid = threadIdx.x;
    int ts = tid >> 2, tt = tid & 3;
    ull acc[4][2];
#pragma unroll
    for (int r = 0; r < 4; ++r) { acc[r][0] = 0ULL; acc[r][1] = 0ULL; }
    for (int cch = 0; cch < 8; ++cch) {
        int k0 = cch * 32;
        for (int idx = tid; idx < SN * 32; idx += 128) {
            int s = idx >> 5, kk = idx & 31;
            A[s][kk] = g_ht[((size_t)(b * SN + s)) * DT + k0 + kk];
        }
        for (int idx = tid; idx < 16 * 32; idx += 128) {
            int t = idx >> 5, kk = idx & 31;
            Bs[kk][t] = -g_mt[((size_t)(b * TN + t0 + t)) * DT + k0 + kk];
        }
        __syncthreads();
#pragma unroll 4
        for (int kk = 0; kk < 32; ++kk) {
            ull bq0 = ld64s(&Bs[kk][tt * 4]);
            ull bq1 = ld64s(&Bs[kk][tt * 4 + 2]);
#pragma unroll
            for (int r = 0; r < 4; ++r) {
                float av = A[ts * 4 + r][kk];
                ull ap = pk2(av, av);
                ull d0 = add2(ap, bq0);
                acc[r][0] = fma2(d0, d0, acc[r][0]);
                ull d1 = add2(ap, bq1);
                acc[r][1] = fma2(d1, d1, acc[r][1]);
            }
        }
        __syncthreads();
    }
    int tok = tokl[b];
#pragma unroll
    for (int r = 0; r < 4; ++r) {
        int s = ts * 4 + r;
        float v[4];
        upk2(acc[r][0], v[0], v[1]);
        upk2(acc[r][1], v[2], v[3]);
#pragma unroll
        for (int j = 0; j < 4; ++j) {
            float dd = (s < tok) ? sqrtf(fmaxf(v[j], 0.f)) : 0.f;
            Z[s][tt * 4 + j] = -dd;
        }
    }
    __syncthreads();
    int tcol = tid >> 3, l = tid & 7;
    float mx = -3.4e38f;
#pragma unroll
    for (int i2 = 0; i2 < 16; ++i2) mx = fmaxf(mx, Z[l * 16 + i2][tcol]);
    mx = fmaxf(mx, __shfl_xor_sync(0xffffffffu, mx, 4));
    mx = fmaxf(mx, __shfl_xor_sync(0xffffffffu, mx, 2));
    mx = fmaxf(mx, __shfl_xor_sync(0xffffffffu, mx, 1));
    float sm = 0.f;
#pragma unroll
    for (int i2 = 0; i2 < 16; ++i2) sm += expf(Z[l * 16 + i2][tcol] - mx);
    sm += __shfl_xor_sync(0xffffffffu, sm, 4);
    sm += __shfl_xor_sync(0xffffffffu, sm, 2);
    sm += __shfl_xor_sync(0xffffffffu, sm, 1);
    if (l == 0) mls[tcol] = mx + logf(sm);
    __syncthreads();
    float* out_log = out + BN * SN;
    float* out_hard = out + BN * SN + (size_t)BN * SN * TN;
    for (int idx = tid; idx < SN * 16; idx += 128) {
        int s = idx >> 4, tl = idx & 15;
        size_t o = ((size_t)(b * SN + s)) * TN + t0 + tl;
        out_log[o] = Z[s][tl] - mls[tl];
        out_hard[o] = 0.f;
    }
    // transposed copy for MAS (s fastest -> coalesced)
    for (int idx = tid; idx < 16 * SN; idx += 128) {
        int tl = idx >> 7, s = idx & 127;
        g_lpT[((size_t)(b * TN) + t0 + tl) * SN + s] = Z[s][tl] - mls[tl];
    }
}

// --------------------------------------------------------------------------
// MAS v2: shared buffer [j][s] -> conflict-free LDS.128; pipelined shfl.
// --------------------------------------------------------------------------
__global__ __launch_bounds__(128) void mas_kernel(const int* __restrict__ tokl,
                                                  const int* __restrict__ featl,
                                                  float* __restrict__ out) {
    const int CH = 16;
    __shared__ __align__(16) float lpbuf[2][CH][SN];
    __shared__ unsigned char ch[TN][32];
    __shared__ int dsh[SN];
    int b = blockIdx.x;
    int tid = threadIdx.x;
    float* hard = out + BN * SN + (size_t)BN * SN * TN + ((size_t)b * SN) * TN;
    float* dout = out + (size_t)b * SN;
    const float* lpT = g_lpT + ((size_t)b * TN) * SN;
    dsh[tid] = 0;
    // preload chunk 0: thread tid owns column s=tid of rows j=0..15
#pragma unroll
    for (int jj = 0; jj < CH; ++jj) lpbuf[0][jj][tid] = lpT[(size_t)jj * SN + tid];
    __syncthreads();
    int ln = tid & 31, wid = tid >> 5;
    float q0 = NEGV, q1 = NEGV, q2 = NEGV, q3 = NEGV, up = NEGV;
    const int NCH = TN / CH;
    for (int c = 0; c < NCH; ++c) {
        if (c + 1 < NCH) {
            const float* src = lpT + ((size_t)(c + 1) * CH) * SN + tid;
            float* dst = &lpbuf[(c + 1) & 1][0][tid];
#pragma unroll
            for (int jj = 0; jj < CH; ++jj) dst[jj * SN] = src[(size_t)jj * SN];
        }
        if (wid == 0) {
            const float(*L)[SN] = lpbuf[c & 1];
#pragma unroll
            for (int jj = 0; jj < CH; ++jj) {
                int j = c * CH + jj;
                float4 Lq = *reinterpret_cast<const float4*>(&L[jj][4 * ln]);
                if (j == 0) {
                    q0 = (ln == 0) ? Lq.x : NEGV;
                    q1 = NEGV; q2 = NEGV; q3 = NEGV;
                    ch[0][ln] = 0;
                    up = __shfl_up_sync(0xffffffffu, q3, 1);
                } else {
                    float s0 = (ln == 0) ? NEGV : up;
                    unsigned bits = (unsigned)(s0 >= q0)
                                  | ((unsigned)(q0 >= q1) << 1)
                                  | ((unsigned)(q1 >= q2) << 2)
                                  | ((unsigned)(q2 >= q3) << 3);
                    float n0 = Lq.x + fmaxf(q0, s0);
                    float n1 = Lq.y + fmaxf(q1, q0);
                    float n2 = Lq.z + fmaxf(q2, q1);
                    float n3 = Lq.w + fmaxf(q3, q2);
                    q0 = n0; q1 = n1; q2 = n2; q3 = n3;
                    ch[j][ln] = (unsigned char)bits;
                    up = __shfl_up_sync(0xffffffffu, q3, 1);
                }
            }
        }
        __syncthreads();
    }
    if (tid == 0) {
        int i = tokl[b] - 1;
        int fl = featl[b];
        for (int j = TN - 1; j >= 0; --j) {
            if (j < fl) {
                hard[(size_t)i * TN + j] = 1.0f;
                dsh[i] += 1;
                int bit = (ch[j][i >> 2] >> (i & 3)) & 1;
                if (j > 0) i -= bit;
            }
        }
    }
    __syncthreads();
    dout[tid] = (float)dsh[tid];
}

extern "C" void kernel_launch(void* const* d_in, const int* in_sizes, int n_in,
                              void* d_out, int out_size) {
    const float* h  = (const float*)d_in[0];
    const float* m  = (const float*)d_in[1];
    const int* tokl = (const int*)d_in[2];
    const int* fetl = (const int*)d_in[3];
    const float* W1 = (const float*)d_in[5];
    const float* b1 = (const float*)d_in[6];
    const float* W2 = (const float*)d_in[7];
    const float* b2 = (const float*)d_in[8];
    const float* F1 = (const float*)d_in[9];
    const float* g1 = (const float*)d_in[10];
    const float* F2 = (const float*)d_in[11];
    const float* g2 = (const float*)d_in[12];
    const float* F3 = (const float*)d_in[13];
    const float* g3 = (const float*)d_in[14];
    float* out = (float*)d_out;

    transpose_kernel<<<576, 256>>>(W1, W2, F1, F2, F3);
    conv_all_kernel<<<320, 256>>>(h, m, b1, b2, g1, g2, g3);
    dist_softmax_kernel<<<dim3(BN, TN / 16), 128>>>(tokl, out);
    mas_kernel<<<BN, 128>>>(tokl, fetl, out);
}